// round 7
// baseline (speedup 1.0000x reference)
#include <cuda_runtime.h>
#include <cstdint>
#include <cstddef>

// ---------------------------------------------------------------------------
// LMPNN encoder: B=8192, N=9, D=1024, H=4096; terms [2,4,6,8]:
//   agg[t=2] = 3*(e4-e3)       + 0.1*e2
//   agg[t=4] = 3*(e2+e3+e6-e5) + 0.1*e4
//   agg[t=6] = 3*(e4+e5+e8-e7) + 0.1*e6
//   agg[t=8] = 3*(e6+e7)       + 0.1*e8
//   out[t]   = relu(agg @ W1 + b1) @ W2 + b2   -> (4, 8192, 1024)
//
// tcgen05 is unavailable (harness lowers via compute_103 PTX; arch-'a'
// features rejected), so the GEMMs use mma.sync.m16n8k8.tf32 tuned for
// occupancy: 512 threads/CTA, warp tile 32x32 (32 acc regs/thread),
// 3-stage cp.async pipeline. All operands pre-rounded to tf32 (cvt.rna)
// at production time -> zero conversions in the inner loop.
// ---------------------------------------------------------------------------

namespace {
constexpr int B_N   = 8192;
constexpr int NODES = 9;
constexpr int D_DIM = 1024;
constexpr int H_DIM = 4096;
constexpr int TERMS = 4;
constexpr int M_TOT = TERMS * B_N;  // 32768
}

// Scratch (allocation-free rule: __device__ globals)
__device__ float g_agg[(size_t)TERMS * B_N * D_DIM];   // 128 MB (tf32-rounded)
__device__ float g_hid[(size_t)TERMS * B_N * H_DIM];   // 512 MB (tf32-rounded)
__device__ float g_w1r[(size_t)D_DIM * H_DIM];         // 16 MB  (tf32-rounded W1)
__device__ float g_w2r[(size_t)H_DIM * D_DIM];         // 4 MB   (tf32-rounded W2)

__device__ __forceinline__ unsigned f2tf(float x) {
    unsigned r;
    asm("cvt.rna.tf32.f32 %0, %1;" : "=r"(r) : "f"(x));
    return r;
}
__device__ __forceinline__ float f2tf_f(float x) {
    return __uint_as_float(f2tf(x));
}

// ---------------------------------------------------------------------------
// Aggregation kernel: one thread per (b, k-float4); tf32-rounded outputs.
// ---------------------------------------------------------------------------
__device__ __forceinline__ float4 f4_comb3(float ca, float4 a, float cb, float4 b,
                                           float cc, float4 c) {
    float4 r;
    r.x = f2tf_f(ca*a.x + cb*b.x + cc*c.x);
    r.y = f2tf_f(ca*a.y + cb*b.y + cc*c.y);
    r.z = f2tf_f(ca*a.z + cb*b.z + cc*c.z);
    r.w = f2tf_f(ca*a.w + cb*b.w + cc*c.w);
    return r;
}
__device__ __forceinline__ float4 f4_comb5(float ca, float4 a, float cb, float4 b,
                                           float cc, float4 c, float cd, float4 d,
                                           float ce, float4 e) {
    float4 r;
    r.x = f2tf_f(ca*a.x + cb*b.x + cc*c.x + cd*d.x + ce*e.x);
    r.y = f2tf_f(ca*a.y + cb*b.y + cc*c.y + cd*d.y + ce*e.y);
    r.z = f2tf_f(ca*a.z + cb*b.z + cc*c.z + cd*d.z + ce*e.z);
    r.w = f2tf_f(ca*a.w + cb*b.w + cc*c.w + cd*d.w + ce*e.w);
    return r;
}

__global__ void agg_kernel(const float* __restrict__ emb) {
    constexpr int KV = D_DIM / 4;  // 256 float4 per row
    size_t idx = (size_t)blockIdx.x * blockDim.x + threadIdx.x;
    if (idx >= (size_t)B_N * KV) return;
    int b  = (int)(idx / KV);
    int kv = (int)(idx % KV);

    const float4* e4p = reinterpret_cast<const float4*>(emb);
    size_t base = ((size_t)b * NODES) * KV + kv;
    float4 n2 = e4p[base + 2*KV];
    float4 n3 = e4p[base + 3*KV];
    float4 n4 = e4p[base + 4*KV];
    float4 n5 = e4p[base + 5*KV];
    float4 n6 = e4p[base + 6*KV];
    float4 n7 = e4p[base + 7*KV];
    float4 n8 = e4p[base + 8*KV];

    float4* A = reinterpret_cast<float4*>(g_agg);
    size_t tstride = (size_t)B_N * KV;
    size_t o = (size_t)b * KV + kv;

    A[o + 0*tstride] = f4_comb3(0.1f, n2, -3.0f, n3, 3.0f, n4);
    A[o + 1*tstride] = f4_comb5(3.0f, n2, 3.0f, n3, 0.1f, n4, -3.0f, n5, 3.0f, n6);
    A[o + 2*tstride] = f4_comb5(3.0f, n4, 3.0f, n5, 0.1f, n6, -3.0f, n7, 3.0f, n8);
    A[o + 3*tstride] = f4_comb3(3.0f, n6, 3.0f, n7, 0.1f, n8);
}

// ---------------------------------------------------------------------------
// Weight prep: round W1 and W2 to tf32 once per launch (~5M floats).
// ---------------------------------------------------------------------------
__global__ void prep_w_kernel(const float* __restrict__ W1,
                              const float* __restrict__ W2) {
    constexpr size_t N1 = (size_t)D_DIM * H_DIM / 4;
    constexpr size_t N2 = (size_t)H_DIM * D_DIM / 4;
    size_t idx = (size_t)blockIdx.x * blockDim.x + threadIdx.x;
    if (idx < N1) {
        float4 v = reinterpret_cast<const float4*>(W1)[idx];
        v.x = f2tf_f(v.x); v.y = f2tf_f(v.y);
        v.z = f2tf_f(v.z); v.w = f2tf_f(v.w);
        reinterpret_cast<float4*>(g_w1r)[idx] = v;
    } else if (idx < N1 + N2) {
        size_t j = idx - N1;
        float4 v = reinterpret_cast<const float4*>(W2)[j];
        v.x = f2tf_f(v.x); v.y = f2tf_f(v.y);
        v.z = f2tf_f(v.z); v.w = f2tf_f(v.w);
        reinterpret_cast<float4*>(g_w2r)[j] = v;
    }
}

// ---------------------------------------------------------------------------
// TF32 tensor-core GEMM: C[M,N] = op(A[M,K] @ B[K,N] + bias[N])
// Inputs pre-rounded tf32 (raw bits -> mma). CTA tile 128x128x32,
// 512 threads = 16 warps (4x4), warp tile 32x32 (mt=2 x m16, nt=4 x n8),
// acc 32 regs/thread. 3-stage cp.async ring.
// op: RELU_TF32 -> relu + tf32-round (feeds next GEMM).
// ---------------------------------------------------------------------------
template <bool RELU_TF32>
__global__ void __launch_bounds__(512, 1)
gemm_tf32(const float* __restrict__ A, const float* __restrict__ Bm,
          const float* __restrict__ bias, float* __restrict__ C,
          int M, int N, int K)
{
    constexpr int BM = 128, BN = 128, BK = 32;
    constexpr int STAGES = 3;
    constexpr int AS_STRIDE = BK + 4;      // 36: conflict-free frag loads
    constexpr int BS_STRIDE = BN + 8;      // 136
    constexpr int AS_BUF = BM * AS_STRIDE; // 4608 floats
    constexpr int BS_BUF = BK * BS_STRIDE; // 4352 floats
    constexpr int STAGE_F = AS_BUF + BS_BUF;  // 8960 floats / stage

    extern __shared__ float smem[];

    const int tid  = threadIdx.x;
    const int lane = tid & 31;
    const int warp = tid >> 5;          // 0..15
    const int warp_m = warp >> 2;       // 0..3
    const int warp_n = warp & 3;        // 0..3
    const int m_cta = blockIdx.y * BM;
    const int n_cta = blockIdx.x * BN;

    // Loader mapping: 1024 16B chunks per operand tile, 2 per thread.
    // A chunk c: row=c>>3 (0..127), kq=c&7.  B chunk c: k=c>>5, nq=c&31.
    const float* Ag = A + (size_t)m_cta * K;

    auto issue_tile = [&](int kt, int s) {
        const int k0 = kt * BK;
        float* As = smem + s * STAGE_F;
        float* Bs = As + AS_BUF;
        #pragma unroll
        for (int i = 0; i < 2; ++i) {
            int c = tid + i * 512;
            int row = c >> 3, kq = c & 7;
            const float* src = Ag + (size_t)row * K + k0 + kq * 4;
            unsigned dst = (unsigned)__cvta_generic_to_shared(
                As + row * AS_STRIDE + kq * 4);
            asm volatile("cp.async.cg.shared.global [%0], [%1], 16;\n"
                         :: "r"(dst), "l"(src));
        }
        #pragma unroll
        for (int i = 0; i < 2; ++i) {
            int c = tid + i * 512;
            int k = c >> 5, nq = c & 31;
            const float* src = Bm + (size_t)(k0 + k) * N + n_cta + nq * 4;
            unsigned dst = (unsigned)__cvta_generic_to_shared(
                Bs + k * BS_STRIDE + nq * 4);
            asm volatile("cp.async.cg.shared.global [%0], [%1], 16;\n"
                         :: "r"(dst), "l"(src));
        }
        asm volatile("cp.async.commit_group;\n");
    };

    float acc[2][4][4];
    #pragma unroll
    for (int mt = 0; mt < 2; ++mt)
        #pragma unroll
        for (int nt = 0; nt < 4; ++nt)
            #pragma unroll
            for (int r = 0; r < 4; ++r) acc[mt][nt][r] = 0.0f;

    const int KT = K / BK;

    // Prologue: tiles 0,1 into stages 0,1
    issue_tile(0, 0);
    issue_tile(1, 1);

    for (int kt = 0; kt < KT; ++kt) {
        if (kt + 2 < KT) issue_tile(kt + 2, (kt + 2) % STAGES);
        // groups newer than tile kt that may stay in flight:
        const int loaded = (kt + 2 < KT) ? kt + 2 : KT - 1;
        const int pend = loaded - kt;
        if (pend >= 2)      asm volatile("cp.async.wait_group 2;\n" ::: "memory");
        else if (pend == 1) asm volatile("cp.async.wait_group 1;\n" ::: "memory");
        else                asm volatile("cp.async.wait_group 0;\n" ::: "memory");
        __syncthreads();

        const unsigned* Asb = reinterpret_cast<const unsigned*>(
            smem + (kt % STAGES) * STAGE_F);
        const unsigned* Bsb = Asb + AS_BUF;

        #pragma unroll
        for (int ks = 0; ks < 4; ++ks) {
            const int kk = ks * 8 + (lane & 3);
            unsigned af[2][4];
            #pragma unroll
            for (int mt = 0; mt < 2; ++mt) {
                int m0 = warp_m * 32 + mt * 16 + (lane >> 2);
                af[mt][0] = Asb[m0 * AS_STRIDE + kk];
                af[mt][1] = Asb[(m0 + 8) * AS_STRIDE + kk];
                af[mt][2] = Asb[m0 * AS_STRIDE + kk + 4];
                af[mt][3] = Asb[(m0 + 8) * AS_STRIDE + kk + 4];
            }
            unsigned bf[4][2];
            #pragma unroll
            for (int nt = 0; nt < 4; ++nt) {
                int n0 = warp_n * 32 + nt * 8 + (lane >> 2);
                bf[nt][0] = Bsb[kk * BS_STRIDE + n0];
                bf[nt][1] = Bsb[(kk + 4) * BS_STRIDE + n0];
            }
            #pragma unroll
            for (int mt = 0; mt < 2; ++mt)
                #pragma unroll
                for (int nt = 0; nt < 4; ++nt) {
                    asm volatile(
                        "mma.sync.aligned.m16n8k8.row.col.f32.tf32.tf32.f32 "
                        "{%0,%1,%2,%3}, {%4,%5,%6,%7}, {%8,%9}, {%0,%1,%2,%3};\n"
                        : "+f"(acc[mt][nt][0]), "+f"(acc[mt][nt][1]),
                          "+f"(acc[mt][nt][2]), "+f"(acc[mt][nt][3])
                        : "r"(af[mt][0]), "r"(af[mt][1]),
                          "r"(af[mt][2]), "r"(af[mt][3]),
                          "r"(bf[nt][0]), "r"(bf[nt][1]));
                }
        }
        __syncthreads();
    }

    // Epilogue: bias (+ relu + tf32-round when feeding next GEMM)
    #pragma unroll
    for (int mt = 0; mt < 2; ++mt) {
        const int rbase = m_cta + warp_m * 32 + mt * 16 + (lane >> 2);
        #pragma unroll
        for (int nt = 0; nt < 4; ++nt) {
            const int col = n_cta + warp_n * 32 + nt * 8 + (lane & 3) * 2;
            const float bv0 = bias[col], bv1 = bias[col + 1];
            float v0 = acc[mt][nt][0] + bv0;
            float v1 = acc[mt][nt][1] + bv1;
            float v2 = acc[mt][nt][2] + bv0;
            float v3 = acc[mt][nt][3] + bv1;
            if (RELU_TF32) {
                v0 = f2tf_f(fmaxf(v0, 0.0f)); v1 = f2tf_f(fmaxf(v1, 0.0f));
                v2 = f2tf_f(fmaxf(v2, 0.0f)); v3 = f2tf_f(fmaxf(v3, 0.0f));
            }
            *reinterpret_cast<float2*>(C + (size_t)rbase * N + col) =
                make_float2(v0, v1);
            *reinterpret_cast<float2*>(C + (size_t)(rbase + 8) * N + col) =
                make_float2(v2, v3);
        }
    }
}

// ---------------------------------------------------------------------------
// Launch
// ---------------------------------------------------------------------------
extern "C" void kernel_launch(void* const* d_in, const int* in_sizes, int n_in,
                              void* d_out, int out_size)
{
    (void)in_sizes; (void)n_in; (void)out_size;
    const float* emb = (const float*)d_in[0];
    const float* W1  = (const float*)d_in[1];
    const float* b1  = (const float*)d_in[2];
    const float* W2  = (const float*)d_in[3];
    const float* b2  = (const float*)d_in[4];
    float* out = (float*)d_out;

    constexpr int STAGE_F = 128 * 36 + 32 * 136;           // 8960 floats
    constexpr int SMEM_BYTES = 3 * STAGE_F * (int)sizeof(float);  // 107520

    cudaFuncSetAttribute(gemm_tf32<true>,
                         cudaFuncAttributeMaxDynamicSharedMemorySize, SMEM_BYTES);
    cudaFuncSetAttribute(gemm_tf32<false>,
                         cudaFuncAttributeMaxDynamicSharedMemorySize, SMEM_BYTES);

    void *pA = nullptr, *pH = nullptr, *pW1 = nullptr, *pW2 = nullptr;
    cudaGetSymbolAddress(&pA, g_agg);
    cudaGetSymbolAddress(&pH, g_hid);
    cudaGetSymbolAddress(&pW1, g_w1r);
    cudaGetSymbolAddress(&pW2, g_w2r);
    float* agg = (float*)pA;
    float* hid = (float*)pH;
    float* w1r = (float*)pW1;
    float* w2r = (float*)pW2;

    // 1) Aggregation (tf32-rounded): (4, 8192, 1024)
    agg_kernel<<<B_N * (D_DIM / 4) / 256, 256>>>(emb);

    // 1b) Round weights to tf32
    {
        const size_t total = ((size_t)D_DIM * H_DIM + (size_t)H_DIM * D_DIM) / 4;
        prep_w_kernel<<<(unsigned)((total + 255) / 256), 256>>>(W1, W2);
    }

    // 2) hid = tf32(relu(agg @ W1 + b1)): M=32768, K=1024, N=4096
    {
        dim3 grid(H_DIM / 128, M_TOT / 128);  // (32, 256)
        gemm_tf32<true><<<grid, 512, SMEM_BYTES>>>(agg, w1r, b1, hid,
                                                   M_TOT, H_DIM, D_DIM);
    }

    // 3) out = hid @ W2 + b2: M=32768, K=4096, N=1024 -> (4,8192,1024)
    {
        dim3 grid(D_DIM / 128, M_TOT / 128);  // (8, 256)
        gemm_tf32<false><<<grid, 512, SMEM_BYTES>>>(hid, w2r, b2, out,
                                                    M_TOT, D_DIM, H_DIM);
    }
}

// round 8
// speedup vs baseline: 2.3841x; 2.3841x over previous
#include <cuda_runtime.h>
#include <cuda_fp16.h>
#include <cstdint>
#include <cstddef>

// ---------------------------------------------------------------------------
// LMPNN encoder: B=8192, N=9, D=1024, H=4096; terms [2,4,6,8]:
//   agg[t=2] = 3*(e4-e3)       + 0.1*e2
//   agg[t=4] = 3*(e2+e3+e6-e5) + 0.1*e4
//   agg[t=6] = 3*(e4+e5+e8-e7) + 0.1*e6
//   agg[t=8] = 3*(e6+e7)       + 0.1*e8
//   out[t]   = relu(agg @ W1 + b1) @ W2 + b2   -> (4, 8192, 1024)
//
// Round-7 analysis: mma.sync GEMM is SHARED-MEMORY-BANDWIDTH bound
// (512 MAC/smem-cyc ceiling == measured 150 TF/s). Fix: fp16 operands
// (same 10-bit mantissa as tf32, half the bytes) + m16n8k16 (2x MACs per
// fragment set) => 1365 MAC/cyc/SM smem ceiling.
// B stored [N,K] fp16 so B-fragments are contiguous u32 loads.
// ---------------------------------------------------------------------------

namespace {
constexpr int B_N   = 8192;
constexpr int NODES = 9;
constexpr int D_DIM = 1024;
constexpr int H_DIM = 4096;
constexpr int TERMS = 4;
constexpr int M_TOT = TERMS * B_N;  // 32768

constexpr int BM = 128, BN = 128, BK = 64;   // BK in fp16 elements
constexpr int STAGES = 3;
constexpr int S_STRIDE = 72;                  // halves; 144B rows, bank-clean
constexpr int AS_BUF = BM * S_STRIDE;         // 9216 halves
constexpr int BS_BUF = BN * S_STRIDE;         // 9216 halves
constexpr int STAGE_H = AS_BUF + BS_BUF;      // 18432 halves = 36864 B
constexpr int SMEM_BYTES = STAGES * STAGE_H * 2;  // 110592 B
}

// Scratch (allocation-free rule: __device__ globals)
__device__ __half g_agg[(size_t)TERMS * B_N * D_DIM];   // 64 MB fp16
__device__ __half g_hid[(size_t)TERMS * B_N * H_DIM];   // 256 MB fp16
__device__ __half g_w1t[(size_t)H_DIM * D_DIM];         // W1^T [H,D] fp16
__device__ __half g_w2t[(size_t)D_DIM * H_DIM];         // W2^T [D,H] fp16

// ---------------------------------------------------------------------------
// Aggregation: one thread per (b, 4 channels); fp16 outputs.
// ---------------------------------------------------------------------------
__global__ void agg_kernel(const float* __restrict__ emb) {
    constexpr int KV = D_DIM / 4;
    size_t idx = (size_t)blockIdx.x * blockDim.x + threadIdx.x;
    if (idx >= (size_t)B_N * KV) return;
    int b  = (int)(idx / KV);
    int kv = (int)(idx % KV);

    const float4* e4p = reinterpret_cast<const float4*>(emb);
    size_t base = ((size_t)b * NODES) * KV + kv;
    float4 n2 = e4p[base + 2*KV];
    float4 n3 = e4p[base + 3*KV];
    float4 n4 = e4p[base + 4*KV];
    float4 n5 = e4p[base + 5*KV];
    float4 n6 = e4p[base + 6*KV];
    float4 n7 = e4p[base + 7*KV];
    float4 n8 = e4p[base + 8*KV];

    __half2* A = reinterpret_cast<__half2*>(g_agg);
    size_t tstride = (size_t)B_N * KV;   // in float4 units
    size_t o = (size_t)b * KV + kv;

    // t=2: 0.1*e2 - 3*e3 + 3*e4
    {
        size_t h = (o + 0 * tstride) * 2;
        A[h]     = __floats2half2_rn(0.1f*n2.x - 3.f*n3.x + 3.f*n4.x,
                                     0.1f*n2.y - 3.f*n3.y + 3.f*n4.y);
        A[h + 1] = __floats2half2_rn(0.1f*n2.z - 3.f*n3.z + 3.f*n4.z,
                                     0.1f*n2.w - 3.f*n3.w + 3.f*n4.w);
    }
    // t=4: 3*(e2+e3+e6-e5) + 0.1*e4
    {
        size_t h = (o + 1 * tstride) * 2;
        A[h]     = __floats2half2_rn(3.f*(n2.x+n3.x+n6.x-n5.x) + 0.1f*n4.x,
                                     3.f*(n2.y+n3.y+n6.y-n5.y) + 0.1f*n4.y);
        A[h + 1] = __floats2half2_rn(3.f*(n2.z+n3.z+n6.z-n5.z) + 0.1f*n4.z,
                                     3.f*(n2.w+n3.w+n6.w-n5.w) + 0.1f*n4.w);
    }
    // t=6: 3*(e4+e5+e8-e7) + 0.1*e6
    {
        size_t h = (o + 2 * tstride) * 2;
        A[h]     = __floats2half2_rn(3.f*(n4.x+n5.x+n8.x-n7.x) + 0.1f*n6.x,
                                     3.f*(n4.y+n5.y+n8.y-n7.y) + 0.1f*n6.y);
        A[h + 1] = __floats2half2_rn(3.f*(n4.z+n5.z+n8.z-n7.z) + 0.1f*n6.z,
                                     3.f*(n4.w+n5.w+n8.w-n7.w) + 0.1f*n6.w);
    }
    // t=8: 3*(e6+e7) + 0.1*e8
    {
        size_t h = (o + 3 * tstride) * 2;
        A[h]     = __floats2half2_rn(3.f*(n6.x+n7.x) + 0.1f*n8.x,
                                     3.f*(n6.y+n7.y) + 0.1f*n8.y);
        A[h + 1] = __floats2half2_rn(3.f*(n6.z+n7.z) + 0.1f*n8.z,
                                     3.f*(n6.w+n7.w) + 0.1f*n8.w);
    }
}

// ---------------------------------------------------------------------------
// Transpose + fp16 round: in[R][C] f32 -> out[C][R] fp16
// ---------------------------------------------------------------------------
__global__ void transpose_half(const float* __restrict__ in,
                               __half* __restrict__ out, int R, int C) {
    __shared__ float t[32][33];
    const int c0 = blockIdx.x * 32, r0 = blockIdx.y * 32;
    const int x = threadIdx.x, y = threadIdx.y;   // block (32, 8)
    #pragma unroll
    for (int dy = 0; dy < 32; dy += 8)
        t[y + dy][x] = in[(size_t)(r0 + y + dy) * C + c0 + x];
    __syncthreads();
    #pragma unroll
    for (int dy = 0; dy < 32; dy += 8)
        out[(size_t)(c0 + y + dy) * R + r0 + x] = __float2half_rn(t[x][y + dy]);
}

// ---------------------------------------------------------------------------
// FP16 tensor-core GEMM: C[M,N] = op(A[M,K] @ Bt[N,K]^T + bias[N])
//   A row-major [M,K] fp16; Bt row-major [N,K] fp16 (pre-transposed weights).
//   CTA 128x128x64, 256 threads = 8 warps (2x4), warp tile 64x32,
//   mma.sync.m16n8k16.f16 with fp32 accum, 3-stage cp.async ring.
//   FUSED: relu + fp16-round, __half out (feeds GEMM2); else float out.
// ---------------------------------------------------------------------------
template <bool FUSED>
__global__ void __launch_bounds__(256, 2)
gemm_fp16(const __half* __restrict__ A, const __half* __restrict__ Bt,
          const float* __restrict__ bias, void* __restrict__ Cv,
          int M, int N, int K)
{
    extern __shared__ __half smem[];

    const int tid  = threadIdx.x;
    const int lane = tid & 31;
    const int warp = tid >> 5;          // 0..7
    const int warp_m = warp >> 2;       // 0..1 (64 rows)
    const int warp_n = warp & 3;        // 0..3 (32 cols)
    const int g  = lane >> 2;           // 0..7
    const int tg = lane & 3;            // 0..3
    const int m_cta = blockIdx.y * BM;
    const int n_cta = blockIdx.x * BN;

    const __half* Ag = A + (size_t)m_cta * K;
    const __half* Bg = Bt + (size_t)n_cta * K;

    // Loader: per operand tile 128 rows x 128B = 1024 x 16B chunks; 4/thread.
    auto issue_tile = [&](int kt, int s) {
        const int k0 = kt * BK;
        __half* As = smem + s * STAGE_H;
        __half* Bs = As + AS_BUF;
        #pragma unroll
        for (int i = 0; i < 4; ++i) {
            int c = tid + i * 256;
            int row = c >> 3, kq = c & 7;           // kq*8 halves = kq*16 B
            const __half* src = Ag + (size_t)row * K + k0 + kq * 8;
            unsigned dst = (unsigned)__cvta_generic_to_shared(
                As + row * S_STRIDE + kq * 8);
            asm volatile("cp.async.cg.shared.global [%0], [%1], 16;\n"
                         :: "r"(dst), "l"(src));
        }
        #pragma unroll
        for (int i = 0; i < 4; ++i) {
            int c = tid + i * 256;
            int row = c >> 3, kq = c & 7;
            const __half* src = Bg + (size_t)row * K + k0 + kq * 8;
            unsigned dst = (unsigned)__cvta_generic_to_shared(
                Bs + row * S_STRIDE + kq * 8);
            asm volatile("cp.async.cg.shared.global [%0], [%1], 16;\n"
                         :: "r"(dst), "l"(src));
        }
        asm volatile("cp.async.commit_group;\n");
    };

    float acc[4][4][4];
    #pragma unroll
    for (int mt = 0; mt < 4; ++mt)
        #pragma unroll
        for (int nt = 0; nt < 4; ++nt)
            #pragma unroll
            for (int r = 0; r < 4; ++r) acc[mt][nt][r] = 0.0f;

    const int KT = K / BK;
    issue_tile(0, 0);
    issue_tile(1, 1);

    for (int kt = 0; kt < KT; ++kt) {
        if (kt + 2 < KT) issue_tile(kt + 2, (kt + 2) % STAGES);
        const int loaded = (kt + 2 < KT) ? kt + 2 : KT - 1;
        const int pend = loaded - kt;
        if (pend >= 2)      asm volatile("cp.async.wait_group 2;\n" ::: "memory");
        else if (pend == 1) asm volatile("cp.async.wait_group 1;\n" ::: "memory");
        else                asm volatile("cp.async.wait_group 0;\n" ::: "memory");
        __syncthreads();

        // 32-bit views; row stride = 36 u32 (72 halves).
        const unsigned* As32 = reinterpret_cast<const unsigned*>(
            smem + (kt % STAGES) * STAGE_H);
        const unsigned* Bs32 = As32 + AS_BUF / 2;

        #pragma unroll
        for (int ks = 0; ks < 4; ++ks) {          // 4 x k16 steps
            const int kk = ks * 8 + tg;           // u32 column index
            unsigned af[4][4];
            #pragma unroll
            for (int mt = 0; mt < 4; ++mt) {
                const int m0 = warp_m * 64 + mt * 16 + g;
                af[mt][0] = As32[m0 * 36 + kk];
                af[mt][1] = As32[(m0 + 8) * 36 + kk];
                af[mt][2] = As32[m0 * 36 + kk + 4];
                af[mt][3] = As32[(m0 + 8) * 36 + kk + 4];
            }
            unsigned bf[4][2];
            #pragma unroll
            for (int nt = 0; nt < 4; ++nt) {
                const int n0 = warp_n * 32 + nt * 8 + g;
                bf[nt][0] = Bs32[n0 * 36 + kk];
                bf[nt][1] = Bs32[n0 * 36 + kk + 4];
            }
            #pragma unroll
            for (int mt = 0; mt < 4; ++mt)
                #pragma unroll
                for (int nt = 0; nt < 4; ++nt) {
                    asm volatile(
                        "mma.sync.aligned.m16n8k16.row.col.f32.f16.f16.f32 "
                        "{%0,%1,%2,%3}, {%4,%5,%6,%7}, {%8,%9}, {%0,%1,%2,%3};\n"
                        : "+f"(acc[mt][nt][0]), "+f"(acc[mt][nt][1]),
                          "+f"(acc[mt][nt][2]), "+f"(acc[mt][nt][3])
                        : "r"(af[mt][0]), "r"(af[mt][1]),
                          "r"(af[mt][2]), "r"(af[mt][3]),
                          "r"(bf[nt][0]), "r"(bf[nt][1]));
                }
        }
        __syncthreads();
    }

    // Epilogue
    #pragma unroll
    for (int mt = 0; mt < 4; ++mt) {
        const int r0 = m_cta + warp_m * 64 + mt * 16 + g;
        #pragma unroll
        for (int nt = 0; nt < 4; ++nt) {
            const int col = n_cta + warp_n * 32 + nt * 8 + tg * 2;
            const float bv0 = bias[col], bv1 = bias[col + 1];
            float v0 = acc[mt][nt][0] + bv0;
            float v1 = acc[mt][nt][1] + bv1;
            float v2 = acc[mt][nt][2] + bv0;
            float v3 = acc[mt][nt][3] + bv1;
            if (FUSED) {
                __half* C = reinterpret_cast<__half*>(Cv);
                __half2* p0 = reinterpret_cast<__half2*>(C + (size_t)r0 * N + col);
                __half2* p1 = reinterpret_cast<__half2*>(C + (size_t)(r0 + 8) * N + col);
                *p0 = __floats2half2_rn(fmaxf(v0, 0.0f), fmaxf(v1, 0.0f));
                *p1 = __floats2half2_rn(fmaxf(v2, 0.0f), fmaxf(v3, 0.0f));
            } else {
                float* C = reinterpret_cast<float*>(Cv);
                *reinterpret_cast<float2*>(C + (size_t)r0 * N + col) =
                    make_float2(v0, v1);
                *reinterpret_cast<float2*>(C + (size_t)(r0 + 8) * N + col) =
                    make_float2(v2, v3);
            }
        }
    }
}

// ---------------------------------------------------------------------------
// Launch
// ---------------------------------------------------------------------------
extern "C" void kernel_launch(void* const* d_in, const int* in_sizes, int n_in,
                              void* d_out, int out_size)
{
    (void)in_sizes; (void)n_in; (void)out_size;
    const float* emb = (const float*)d_in[0];
    const float* W1  = (const float*)d_in[1];
    const float* b1  = (const float*)d_in[2];
    const float* W2  = (const float*)d_in[3];
    const float* b2  = (const float*)d_in[4];
    float* out = (float*)d_out;

    cudaFuncSetAttribute(gemm_fp16<true>,
                         cudaFuncAttributeMaxDynamicSharedMemorySize, SMEM_BYTES);
    cudaFuncSetAttribute(gemm_fp16<false>,
                         cudaFuncAttributeMaxDynamicSharedMemorySize, SMEM_BYTES);

    void *pA = nullptr, *pH = nullptr, *pW1 = nullptr, *pW2 = nullptr;
    cudaGetSymbolAddress(&pA, g_agg);
    cudaGetSymbolAddress(&pH, g_hid);
    cudaGetSymbolAddress(&pW1, g_w1t);
    cudaGetSymbolAddress(&pW2, g_w2t);
    __half* agg = (__half*)pA;
    __half* hid = (__half*)pH;
    __half* w1t = (__half*)pW1;
    __half* w2t = (__half*)pW2;

    // 1) Aggregation -> fp16: (4, 8192, 1024)
    agg_kernel<<<B_N * (D_DIM / 4) / 256, 256>>>(emb);

    // 1b) Weights -> [N,K] fp16
    transpose_half<<<dim3(H_DIM / 32, D_DIM / 32), dim3(32, 8)>>>(
        W1, w1t, D_DIM, H_DIM);   // W1 [D,H] -> w1t [H,D]
    transpose_half<<<dim3(D_DIM / 32, H_DIM / 32), dim3(32, 8)>>>(
        W2, w2t, H_DIM, D_DIM);   // W2 [H,D] -> w2t [D,H]

    // 2) hid = fp16(relu(agg @ W1 + b1)): M=32768, N=4096, K=1024
    {
        dim3 grid(H_DIM / BN, M_TOT / BM);   // (32, 256)
        gemm_fp16<true><<<grid, 256, SMEM_BYTES>>>(agg, w1t, b1, hid,
                                                   M_TOT, H_DIM, D_DIM);
    }

    // 3) out = hid @ W2 + b2: M=32768, N=1024, K=4096 -> (4,8192,1024)
    {
        dim3 grid(D_DIM / BN, M_TOT / BM);   // (8, 256)
        gemm_fp16<false><<<grid, 256, SMEM_BYTES>>>(hid, w2t, b2, out,
                                                    M_TOT, D_DIM, H_DIM);
    }
}